// round 12
// baseline (speedup 1.0000x reference)
#include <cuda_runtime.h>
#include <cuda_fp16.h>
#include <cstdint>
#include <cstddef>

// Problem constants
#define T_STEPS 512
#define BATCH   128
#define DIN     512
#define HID     512
#define G4      2048   // 4*HID

// ---------------------------------------------------------------------------
// Device-global scratch (allocation-free rule)
// ---------------------------------------------------------------------------
__device__ float  g_xg[(size_t)T_STEPS * BATCH * G4];     // xg = x*Wx^T + biases
__device__ __half g_xh[(size_t)T_STEPS * BATCH * DIN];    // x as fp16
__device__ __half g_wxh[(size_t)G4 * DIN];                // Wx as fp16
__device__ __half g_hbuf[2][(size_t)BATCH * HID];         // h as fp16, dbl-buf
__device__ unsigned int g_flag[4][T_STEPS][32];           // barrier flags
__device__ unsigned int g_exit;

// ---------------------------------------------------------------------------
// helpers
// ---------------------------------------------------------------------------
__device__ __forceinline__ void mma_f16(float* d,
    uint32_t a0, uint32_t a1, uint32_t a2, uint32_t a3,
    uint32_t b0, uint32_t b1)
{
    asm volatile(
        "mma.sync.aligned.m16n8k16.row.col.f32.f16.f16.f32 "
        "{%0,%1,%2,%3}, {%4,%5,%6,%7}, {%8,%9}, {%0,%1,%2,%3};\n"
        : "+f"(d[0]), "+f"(d[1]), "+f"(d[2]), "+f"(d[3])
        : "r"(a0), "r"(a1), "r"(a2), "r"(a3), "r"(b0), "r"(b1));
}

__device__ __forceinline__ void ldsm4(uint32_t* r, uint32_t addr) {
    asm volatile(
        "ldmatrix.sync.aligned.m8n8.x4.shared.b16 {%0,%1,%2,%3}, [%4];"
        : "=r"(r[0]), "=r"(r[1]), "=r"(r[2]), "=r"(r[3]) : "r"(addr));
}

__device__ __forceinline__ void cp16(uint32_t dst, const void* src) {
    asm volatile("cp.async.cg.shared.global [%0], [%1], 16;" :: "r"(dst), "l"(src));
}
__device__ __forceinline__ void cp_commit() {
    asm volatile("cp.async.commit_group;");
}
template <int N>
__device__ __forceinline__ void cp_wait() {
    asm volatile("cp.async.wait_group %0;" :: "n"(N));
}

#define BAR_SYNC(id, n) \
    asm volatile("bar.sync %0, %1;" :: "r"(id), "r"(n) : "memory")

__device__ __forceinline__ float fsigmoid(float x) {
    return __fdividef(1.0f, 1.0f + __expf(-x));
}
__device__ __forceinline__ float ftanh(float x) {
    float e = __expf(-2.0f * x);
    return __fdividef(2.0f, 1.0f + e) - 1.0f;
}

// ===========================================================================
// Prologue: fp32 -> fp16 conversion
// ===========================================================================
__global__ void cvt_f16_kernel(const float* __restrict__ src,
                               __half* __restrict__ dst, size_t n4)
{
    size_t i = (size_t)blockIdx.x * blockDim.x + threadIdx.x;
    size_t stride = (size_t)gridDim.x * blockDim.x;
    for (; i < n4; i += stride) {
        float4 v = ((const float4*)src)[i];
        __half2 lo = __floats2half2_rn(v.x, v.y);
        __half2 hi = __floats2half2_rn(v.z, v.w);
        uint2 u;
        u.x = *(uint32_t*)&lo;
        u.y = *(uint32_t*)&hi;
        ((uint2*)dst)[i] = u;
    }
}

// ===========================================================================
// Phase A: xg[m][n] = sum_k x[m][k]*Wx[n][k] + bx[n] + bh[n]   (fp16 mma)
//   R6-proven kernel: block 128x128, BK=32, 256 threads, 2-stage cp.async,
//   pitch-80 SMEM, warp tile 32m x 64n, ldmatrix.x4 fragments.
// ===========================================================================
#define PA_PITCH 80
#define PA_STG   (128 * PA_PITCH)
#define SMEM_A_BYTES (4 * PA_STG)

__global__ __launch_bounds__(256, 2) void gemm_xg_kernel(
    const float* __restrict__ bxp,
    const float* __restrict__ bhp)
{
    extern __shared__ uint8_t smA[];
    const uint32_t sb = (uint32_t)__cvta_generic_to_shared(smA);

    const int tid  = threadIdx.x;
    const int bn   = blockIdx.x * 128;
    const int bm   = blockIdx.y * 128;
    const int warp = tid >> 5;
    const int lane = tid & 31;
    const int wm   = (warp & 3) * 32;
    const int wn   = (warp >> 2) * 64;
    const int g    = lane >> 2;
    const int t    = lane & 3;

    float acc[2][8][4];
#pragma unroll
    for (int i = 0; i < 2; i++)
#pragma unroll
        for (int j = 0; j < 8; j++)
#pragma unroll
            for (int q = 0; q < 4; q++) acc[i][j][q] = 0.0f;

    uint32_t aA0 = (uint32_t)((wm + (lane & 15)) * PA_PITCH + (lane >> 4) * 16);
    uint32_t aA1 = (uint32_t)((wm + 16 + (lane & 15)) * PA_PITCH + (lane >> 4) * 16);
    uint32_t brow = (uint32_t)(wn + (lane & 7) + ((lane >> 4) << 3));
    uint32_t bcol = (uint32_t)(((lane >> 3) & 1) * 16);

    auto issue_stage = [&](int k0, int s) {
#pragma unroll
        for (int i = 0; i < 2; i++) {
            int id = i * 256 + tid;
            int r  = id >> 2;
            int u  = id & 3;
            cp16(sb + (uint32_t)(s * PA_STG + r * PA_PITCH + u * 16),
                 g_xh + (size_t)(bm + r) * DIN + k0 + u * 8);
            cp16(sb + (uint32_t)((2 + s) * PA_STG + r * PA_PITCH + u * 16),
                 g_wxh + (size_t)(bn + r) * DIN + k0 + u * 8);
        }
        cp_commit();
    };

    issue_stage(0, 0);

    for (int it = 0; it < 16; it++) {
        if (it + 1 < 16) {
            issue_stage((it + 1) * 32, (it + 1) & 1);
            cp_wait<1>();
        } else {
            cp_wait<0>();
        }
        __syncthreads();

        uint32_t As = sb + (uint32_t)((it & 1) * PA_STG);
        uint32_t Bs = sb + (uint32_t)((2 + (it & 1)) * PA_STG);

#pragma unroll
        for (int kk = 0; kk < 2; kk++) {
            uint32_t koff = (uint32_t)(kk * 32);
            uint32_t a[2][4], bb[4][4];
            ldsm4(a[0], As + aA0 + koff);
            ldsm4(a[1], As + aA1 + koff);
#pragma unroll
            for (int nt4 = 0; nt4 < 4; nt4++)
                ldsm4(bb[nt4], Bs + (brow + nt4 * 16) * PA_PITCH + bcol + koff);
#pragma unroll
            for (int mt = 0; mt < 2; mt++)
#pragma unroll
                for (int nt = 0; nt < 8; nt++)
                    mma_f16(acc[mt][nt],
                            a[mt][0], a[mt][1], a[mt][2], a[mt][3],
                            bb[nt >> 1][(nt & 1) * 2], bb[nt >> 1][(nt & 1) * 2 + 1]);
        }
        __syncthreads();
    }

#pragma unroll
    for (int mt = 0; mt < 2; mt++) {
        int row0 = bm + wm + mt * 16 + g;
#pragma unroll
        for (int nt = 0; nt < 8; nt++) {
            int col = bn + wn + nt * 8 + 2 * t;
            float bias0 = bxp[col]     + bhp[col];
            float bias1 = bxp[col + 1] + bhp[col + 1];
            float2 v0 = make_float2(acc[mt][nt][0] + bias0, acc[mt][nt][1] + bias1);
            float2 v1 = make_float2(acc[mt][nt][2] + bias0, acc[mt][nt][3] + bias1);
            *(float2*)(g_xg + (size_t)row0 * G4 + col)       = v0;
            *(float2*)(g_xg + (size_t)(row0 + 8) * G4 + col) = v1;
        }
    }
}

// ===========================================================================
// Phase B: persistent recurrence, 128 blocks x 160 threads.
//   Warps 0-3 compute (R8-proven 32m x 16n gate-interleaved mapping);
//   warp 4 loader stages h_{ts-1} (32KB fp16) and xg[ts] (8.5KB fp32,
//   bias included) behind the compute warps' work. Per-step compute chain:
//   barA -> rec-GEMM -> gates -> release. No input-projection GEMM in-loop.
// SMEM: Whs 64x1040 | Hs 32x1040 | Xs 2 x 32x272
// ===========================================================================
#define PB_PITCH 1040
#define WHS_OFF  0u
#define HS_OFF   (64u * PB_PITCH)                   // 66560
#define XS_OFF   (HS_OFF + 32u * PB_PITCH)          // 99840
#define XS_PITCH 272u                               // 68 floats
#define XS_BUF   (32u * XS_PITCH)                   // 8704
#define SMEM_B_BYTES (XS_OFF + 2u * XS_BUF + 64u)   // 117312

#define NTHREADS 160

__global__ __launch_bounds__(NTHREADS, 1) void lstm_rec_kernel(
    const float* __restrict__ Wh,
    float* __restrict__ out)
{
    extern __shared__ uint8_t smB[];
    const uint32_t sb = (uint32_t)__cvta_generic_to_shared(smB);

    const int tid  = threadIdx.x;
    const int warp = tid >> 5;
    const int lane = tid & 31;
    const int g    = lane >> 2;
    const int t    = lane & 3;
    const int odd  = t & 1;

    const int bi = blockIdx.x >> 5;
    const int bj = blockIdx.x & 31;
    const int b0 = bi * 32;
    const int j0 = bj * 16;

    const bool is_loader = (warp == 4);

    // ---- one-time: Wh slice -> SMEM fp16, gate-interleaved rows ----
    for (int idx = tid; idx < 64 * 512; idx += NTHREADS) {
        int n = idx >> 9;
        int k = idx & 511;
        int w = n >> 4, p = n & 15;
        int grow = (p & 3) * HID + j0 + w * 4 + (p >> 2);
        *(__half*)(smB + WHS_OFF + (uint32_t)n * PB_PITCH + (uint32_t)k * 2) =
            __float2half_rn(Wh[(size_t)grow * HID + k]);
    }

    // ---- ldmatrix bases (compute warps; R8 mapping) ----
    uint32_t rowsel = (uint32_t)((lane & 15) * PB_PITCH + (lane >> 4) * 16);
    uint32_t aH0 = sb + HS_OFF + rowsel;
    uint32_t aH1 = sb + HS_OFF + (uint32_t)(16 * PB_PITCH) + rowsel;
    uint32_t brow = (uint32_t)(((warp & 3) * 16 + (lane & 7) + ((lane >> 4) << 3)) * PB_PITCH
                               + ((lane >> 3) & 1) * 16);
    uint32_t aBh = sb + WHS_OFF + brow;

    // ---- loader lambdas (warp 4; lanes cover 16B chunks) ----
    // xg tile: 32 rows x (4 gates x 16 floats) -> Xs rows of 68 floats
    auto load_xg = [&](int tsn) {
        uint32_t dstb = XS_OFF + (uint32_t)(tsn & 1) * XS_BUF;
        const float* src = g_xg + ((size_t)tsn * BATCH + b0) * G4 + j0;
#pragma unroll
        for (int i = 0; i < 16; i++) {
            int id   = i * 32 + lane;      // 0..511
            int r    = id >> 4;            // 0..31
            int u    = id & 15;            // 0..15
            int gate = u >> 2;
            int c4   = u & 3;
            cp16(sb + dstb + (uint32_t)r * XS_PITCH + (uint32_t)(gate * 64 + c4 * 16),
                 src + (size_t)r * G4 + gate * HID + c4 * 4);
        }
        cp_commit();
    };
    auto load_h = [&](int tsp) {
        const __half* src = g_hbuf[tsp & 1] + (size_t)b0 * HID;
#pragma unroll
        for (int i = 0; i < 64; i++) {
            int id = i * 32 + lane;
            int r  = id >> 6;
            int u  = id & 63;
            cp16(sb + HS_OFF + (uint32_t)(r * PB_PITCH + u * 16),
                 src + (size_t)r * HID + u * 8);
        }
        cp_commit();
    };

    float accr[2][2][4];
    float cst[2][2] = {{0.f, 0.f}, {0.f, 0.f}};

    // ---- prologue: loader stages xg[0] ----
    if (is_loader) load_xg(0);
    __syncthreads();        // weights visible (xg[0] drained at first barA)

    for (int ts = 0; ts < T_STEPS; ts++) {
        if (is_loader) {
            // before barA(ts): h_{ts-1} (ts>0) and Xs[ts] must be resident
            cp_wait<0>();
            BAR_SYNC(1, NTHREADS);               // barA(ts)
            if (ts + 1 < T_STEPS) load_xg(ts + 1);
            if (ts < T_STEPS - 1) {
                const unsigned int* fp = &g_flag[bi][ts][lane];
                unsigned v;
                do {
                    asm volatile("ld.acquire.gpu.global.u32 %0, [%1];"
                                 : "=r"(v) : "l"(fp) : "memory");
                    if (v) break;
                    __nanosleep(20);
                } while (true);
                __syncwarp();
                load_h(ts);
            }
        } else {
            BAR_SYNC(1, NTHREADS);               // barA(ts)

            // ---- recurrent GEMM: Hs @ Whs ----
#pragma unroll
            for (int mt = 0; mt < 2; mt++)
#pragma unroll
                for (int nt = 0; nt < 2; nt++)
#pragma unroll
                    for (int q = 0; q < 4; q++) accr[mt][nt][q] = 0.0f;

            if (ts > 0) {
#pragma unroll 4
                for (int s = 0; s < 32; s++) {
                    uint32_t ko = (uint32_t)(s * 32);
                    uint32_t a0[4], a1[4], bb[4];
                    ldsm4(a0, aH0 + ko);
                    ldsm4(a1, aH1 + ko);
                    ldsm4(bb, aBh + ko);
                    mma_f16(accr[0][0], a0[0], a0[1], a0[2], a0[3], bb[0], bb[1]);
                    mma_f16(accr[0][1], a0[0], a0[1], a0[2], a0[3], bb[2], bb[3]);
                    mma_f16(accr[1][0], a1[0], a1[1], a1[2], a1[3], bb[0], bb[1]);
                    mma_f16(accr[1][1], a1[0], a1[1], a1[2], a1[3], bb[2], bb[3]);
                }
            }

            // ---- gates: shuffle + xg from Xs (bias included) ----
            const float* Xs = (const float*)(smB + XS_OFF + (uint32_t)(ts & 1) * XS_BUF);
            float hout[2][2];
#pragma unroll
            for (int mt = 0; mt < 2; mt++) {
#pragma unroll
                for (int nt = 0; nt < 2; nt++) {
                    float q0 = accr[mt][nt][0], q1 = accr[mt][nt][1];
                    float q2 = accr[mt][nt][2], q3 = accr[mt][nt][3];
                    float sx = odd ? q0 : q2;
                    float sy = odd ? q1 : q3;
                    float rx = __shfl_xor_sync(0xffffffffu, sx, 1);
                    float ry = __shfl_xor_sync(0xffffffffu, sy, 1);

                    int rl = mt * 16 + g + (odd << 3);
                    int jl = (warp & 3) * 4 + (t >> 1) + 2 * nt;
                    const float* xrow = Xs + rl * 68 + jl;

                    float gi = (odd ? rx : q0) + xrow[0];
                    float gf = (odd ? ry : q1) + xrow[16];
                    float gg = (odd ? q2 : rx) + xrow[32];
                    float go = (odd ? q3 : ry) + xrow[48];

                    float iv = fsigmoid(gi), fv = fsigmoid(gf);
                    float gv = ftanh(gg),    ov = fsigmoid(go);
                    float cn = cst[mt][nt] * fv + iv * gv;
                    cst[mt][nt] = cn;
                    float h = ov * ftanh(cn);
                    hout[mt][nt] = h;

                    g_hbuf[ts & 1][(size_t)(b0 + rl) * HID + j0 + jl] =
                        __float2half_rn(h);
                }
            }

            BAR_SYNC(2, 128);                    // compute-only: stores ordered

            if (ts < T_STEPS - 1 && tid == 0) {
                asm volatile("st.release.gpu.global.u32 [%0], %1;"
                             :: "l"(&g_flag[bi][ts][bj]), "r"(1u) : "memory");
            }

            // out fp32 stores (off the inter-block critical path)
            {
                float* obase = out + (size_t)ts * (BATCH * HID);
#pragma unroll
                for (int mt = 0; mt < 2; mt++)
#pragma unroll
                    for (int nt = 0; nt < 2; nt++) {
                        int rl = mt * 16 + g + (odd << 3);
                        int jl = (warp & 3) * 4 + (t >> 1) + 2 * nt;
                        obase[(size_t)(b0 + rl) * HID + j0 + jl] = hout[mt][nt];
                    }
            }
        }
    }

    // ---- exit: last block resets barrier state for next graph replay ----
    __syncthreads();
    volatile unsigned* rflag = (volatile unsigned*)(smB + XS_OFF);
    if (tid == 0) {
        unsigned old;
        asm volatile("atom.acq_rel.gpu.add.u32 %0, [%1], 1;"
                     : "=r"(old) : "l"(&g_exit) : "memory");
        *rflag = (old == 127u) ? 1u : 0u;
    }
    __syncthreads();
    if (*rflag != 0u) {
        unsigned int* fl = &g_flag[0][0][0];
        for (int i = tid; i < 4 * T_STEPS * 32; i += NTHREADS) fl[i] = 0u;
        __threadfence();
        if (tid == 0) g_exit = 0u;
    }
}

// ===========================================================================
// Launch
// ===========================================================================
extern "C" void kernel_launch(void* const* d_in, const int* in_sizes, int n_in,
                              void* d_out, int out_size)
{
    (void)in_sizes; (void)n_in; (void)out_size;
    const float* x  = (const float*)d_in[0];
    const float* Wx = (const float*)d_in[1];
    const float* bx = (const float*)d_in[2];
    const float* Wh = (const float*)d_in[3];
    const float* bh = (const float*)d_in[4];
    float* out = (float*)d_out;

    __half* xh;  cudaGetSymbolAddress((void**)&xh,  g_xh);
    __half* wxh; cudaGetSymbolAddress((void**)&wxh, g_wxh);

    cudaFuncSetAttribute(gemm_xg_kernel,
                         cudaFuncAttributeMaxDynamicSharedMemorySize, SMEM_A_BYTES);
    cudaFuncSetAttribute(lstm_rec_kernel,
                         cudaFuncAttributeMaxDynamicSharedMemorySize, SMEM_B_BYTES);

    // fp32 -> fp16
    cvt_f16_kernel<<<2048, 256>>>(x,  xh,  (size_t)T_STEPS * BATCH * DIN / 4);
    cvt_f16_kernel<<<512,  256>>>(Wx, wxh, (size_t)G4 * DIN / 4);

    // Phase A: xg = x*Wx^T + bx + bh
    gemm_xg_kernel<<<dim3(G4 / 128, (T_STEPS * BATCH) / 128), 256, SMEM_A_BYTES>>>(bx, bh);

    // Phase B: persistent recurrence
    lstm_rec_kernel<<<128, NTHREADS, SMEM_B_BYTES>>>(Wh, out);
}

// round 13
// speedup vs baseline: 1.2926x; 1.2926x over previous
#include <cuda_runtime.h>
#include <cuda_fp16.h>
#include <cstdint>
#include <cstddef>

// Problem constants
#define T_STEPS 512
#define BATCH   128
#define DIN     512
#define HID     512
#define G4      2048   // 4*HID

// ---------------------------------------------------------------------------
// Device-global scratch (allocation-free rule)
// ---------------------------------------------------------------------------
__device__ __half g_xh[(size_t)T_STEPS * BATCH * DIN];    // x as fp16
__device__ __half g_hbuf[2][(size_t)BATCH * HID];         // h as fp16, dbl-buf
__device__ unsigned int g_flag[4][T_STEPS][32];           // barrier flags
__device__ unsigned int g_exit;

// ---------------------------------------------------------------------------
// helpers
// ---------------------------------------------------------------------------
__device__ __forceinline__ void mma_f16(float* d,
    uint32_t a0, uint32_t a1, uint32_t a2, uint32_t a3,
    uint32_t b0, uint32_t b1)
{
    asm volatile(
        "mma.sync.aligned.m16n8k16.row.col.f32.f16.f16.f32 "
        "{%0,%1,%2,%3}, {%4,%5,%6,%7}, {%8,%9}, {%0,%1,%2,%3};\n"
        : "+f"(d[0]), "+f"(d[1]), "+f"(d[2]), "+f"(d[3])
        : "r"(a0), "r"(a1), "r"(a2), "r"(a3), "r"(b0), "r"(b1));
}

__device__ __forceinline__ void ldsm4(uint32_t* r, uint32_t addr) {
    asm volatile(
        "ldmatrix.sync.aligned.m8n8.x4.shared.b16 {%0,%1,%2,%3}, [%4];"
        : "=r"(r[0]), "=r"(r[1]), "=r"(r[2]), "=r"(r[3]) : "r"(addr));
}

__device__ __forceinline__ void cp16(uint32_t dst, const void* src) {
    asm volatile("cp.async.cg.shared.global [%0], [%1], 16;" :: "r"(dst), "l"(src));
}
__device__ __forceinline__ void cp_commit() {
    asm volatile("cp.async.commit_group;");
}
template <int N>
__device__ __forceinline__ void cp_wait() {
    asm volatile("cp.async.wait_group %0;" :: "n"(N));
}

#define BAR_SYNC(id, n) \
    asm volatile("bar.sync %0, %1;" :: "r"(id), "r"(n) : "memory")

__device__ __forceinline__ float fsigmoid(float x) {
    return __fdividef(1.0f, 1.0f + __expf(-x));
}
__device__ __forceinline__ float ftanh(float x) {
    float e = __expf(-2.0f * x);
    return __fdividef(2.0f, 1.0f + e) - 1.0f;
}

// ===========================================================================
// Prologue: fp32 -> fp16 conversion (x only)
// ===========================================================================
__global__ void cvt_f16_kernel(const float* __restrict__ src,
                               __half* __restrict__ dst, size_t n4)
{
    size_t i = (size_t)blockIdx.x * blockDim.x + threadIdx.x;
    size_t stride = (size_t)gridDim.x * blockDim.x;
    for (; i < n4; i += stride) {
        float4 v = ((const float4*)src)[i];
        __half2 lo = __floats2half2_rn(v.x, v.y);
        __half2 hi = __floats2half2_rn(v.z, v.w);
        uint2 u;
        u.x = *(uint32_t*)&lo;
        u.y = *(uint32_t*)&hi;
        ((uint2*)dst)[i] = u;
    }
}

// ===========================================================================
// Fused persistent LSTM, 128 blocks x 160 threads (R10 structure):
//   warps 0-3 compute (32m x 16n gate-interleaved), warp 4 loader.
//   Loader hides flag-poll + h cp.async behind the compute warps' fused
//   input-projection GEMM. THIS ROUND: both GEMM k-loops are 2-stage
//   software-pipelined (ldsm for s+1 before mma of s) to pull the LDS
//   latency off the serial chain.
// ===========================================================================
#define PB_PITCH 1040                               // 512 halves + 16B pad
#define WHS_OFF  0u
#define WXS_OFF  (64u * PB_PITCH)                   // 66560
#define HS_OFF   (WXS_OFF + 64u * PB_PITCH)         // 133120
#define XH_OFF   (HS_OFF + 32u * PB_PITCH)          // 166400
#define SMEM_B_BYTES (XH_OFF + 32u * PB_PITCH + 64) // 199744

#define NTHREADS 160

__global__ __launch_bounds__(NTHREADS, 1) void lstm_rec_kernel(
    const float* __restrict__ Wh,
    const float* __restrict__ Wx,
    const float* __restrict__ bxp,
    const float* __restrict__ bhp,
    float* __restrict__ out)
{
    extern __shared__ uint8_t smB[];
    const uint32_t sb = (uint32_t)__cvta_generic_to_shared(smB);

    const int tid  = threadIdx.x;
    const int warp = tid >> 5;
    const int lane = tid & 31;
    const int g    = lane >> 2;
    const int t    = lane & 3;
    const int odd  = t & 1;

    const int bi = blockIdx.x >> 5;
    const int bj = blockIdx.x & 31;
    const int b0 = bi * 32;
    const int j0 = bj * 16;

    const bool is_loader = (warp == 4);

    // ---- one-time: Wh and Wx slices -> SMEM fp16, gate-interleaved rows ----
    for (int idx = tid; idx < 64 * 512; idx += NTHREADS) {
        int n = idx >> 9;
        int k = idx & 511;
        int w = n >> 4, p = n & 15;
        int grow = (p & 3) * HID + j0 + w * 4 + (p >> 2);
        *(__half*)(smB + WHS_OFF + (uint32_t)n * PB_PITCH + (uint32_t)k * 2) =
            __float2half_rn(Wh[(size_t)grow * HID + k]);
        *(__half*)(smB + WXS_OFF + (uint32_t)n * PB_PITCH + (uint32_t)k * 2) =
            __float2half_rn(Wx[(size_t)grow * DIN + k]);
    }

    // ---- bias registers (compute warps only) ----
    float bias[2][4];
    if (!is_loader) {
#pragma unroll
        for (int nt = 0; nt < 2; nt++) {
            int jc = j0 + warp * 4 + (t >> 1) + 2 * nt;
#pragma unroll
            for (int gate = 0; gate < 4; gate++)
                bias[nt][gate] = bxp[gate * HID + jc] + bhp[gate * HID + jc];
        }
    }

    // ---- ldmatrix bases (compute warps; R8 mapping) ----
    uint32_t rowsel = (uint32_t)((lane & 15) * PB_PITCH + (lane >> 4) * 16);
    uint32_t aH0 = sb + HS_OFF + rowsel;
    uint32_t aH1 = sb + HS_OFF + (uint32_t)(16 * PB_PITCH) + rowsel;
    uint32_t aX0 = sb + XH_OFF + rowsel;
    uint32_t aX1 = sb + XH_OFF + (uint32_t)(16 * PB_PITCH) + rowsel;
    uint32_t brow = (uint32_t)(((warp & 3) * 16 + (lane & 7) + ((lane >> 4) << 3)) * PB_PITCH
                               + ((lane >> 3) & 1) * 16);
    uint32_t aBh = sb + WHS_OFF + brow;
    uint32_t aBx = sb + WXS_OFF + brow;

    // ---- loader lambdas (warp 4; 64 chunks of 16B per lane) ----
    auto load_x = [&](int tsn) {
        const __half* src = g_xh + ((size_t)tsn * BATCH + b0) * DIN;
#pragma unroll
        for (int i = 0; i < 64; i++) {
            int id = i * 32 + lane;
            int r  = id >> 6;
            int u  = id & 63;
            cp16(sb + XH_OFF + (uint32_t)(r * PB_PITCH + u * 16),
                 src + (size_t)r * DIN + u * 8);
        }
        cp_commit();
    };
    auto load_h = [&](int tsp) {
        const __half* src = g_hbuf[tsp & 1] + (size_t)b0 * HID;
#pragma unroll
        for (int i = 0; i < 64; i++) {
            int id = i * 32 + lane;
            int r  = id >> 6;
            int u  = id & 63;
            cp16(sb + HS_OFF + (uint32_t)(r * PB_PITCH + u * 16),
                 src + (size_t)r * HID + u * 8);
        }
        cp_commit();
    };

    float accx[2][2][4];
    float accr[2][2][4];
    float cst[2][2] = {{0.f, 0.f}, {0.f, 0.f}};

    // 2-stage pipelined GEMM core: acc += A(32x512) @ B(16x512)^T
    auto gemm_pipe = [&](uint32_t A0, uint32_t A1, uint32_t B, float (*acc)[2][4]) {
        uint32_t a0[2][4], a1[2][4], bb[2][4];
        ldsm4(a0[0], A0);
        ldsm4(a1[0], A1);
        ldsm4(bb[0], B);
#pragma unroll 4
        for (int s = 0; s < 32; s++) {
            int cur = s & 1, nxt = cur ^ 1;
            if (s < 31) {
                uint32_t ko = (uint32_t)((s + 1) * 32);
                ldsm4(a0[nxt], A0 + ko);
                ldsm4(a1[nxt], A1 + ko);
                ldsm4(bb[nxt], B + ko);
            }
            mma_f16(acc[0][0], a0[cur][0], a0[cur][1], a0[cur][2], a0[cur][3],
                    bb[cur][0], bb[cur][1]);
            mma_f16(acc[0][1], a0[cur][0], a0[cur][1], a0[cur][2], a0[cur][3],
                    bb[cur][2], bb[cur][3]);
            mma_f16(acc[1][0], a1[cur][0], a1[cur][1], a1[cur][2], a1[cur][3],
                    bb[cur][0], bb[cur][1]);
            mma_f16(acc[1][1], a1[cur][0], a1[cur][1], a1[cur][2], a1[cur][3],
                    bb[cur][2], bb[cur][3]);
        }
    };

    auto xg_gemm = [&]() {
#pragma unroll
        for (int mt = 0; mt < 2; mt++)
#pragma unroll
            for (int nt = 0; nt < 2; nt++)
#pragma unroll
                for (int q = 0; q < 4; q++) accx[mt][nt][q] = 0.0f;
        gemm_pipe(aX0, aX1, aBx, accx);
    };

    // ---- prologue: x[0] -> Xh (loader), xg-gemm for ts=0 (compute) ----
    if (is_loader) { load_x(0); cp_wait<0>(); }
    __syncthreads();        // weights + x[0] visible to all
    if (!is_loader) xg_gemm();

    for (int ts = 0; ts < T_STEPS; ts++) {
        if (is_loader) {
            if (ts > 0) {
                // poll flags (one per lane), then pull h_{ts-1}
                const unsigned int* fp = &g_flag[bi][ts - 1][lane];
                unsigned v;
                do {
                    asm volatile("ld.acquire.gpu.global.u32 %0, [%1];"
                                 : "=r"(v) : "l"(fp) : "memory");
                } while (!v);
                __syncwarp();
                load_h(ts - 1);
                cp_wait<0>();
            }
            BAR_SYNC(1, NTHREADS);             // barA: h ready / Xh consumed
            if (ts + 1 < T_STEPS) {
                load_x(ts + 1);
                cp_wait<0>();
                BAR_SYNC(3, NTHREADS);         // barB: x[ts+1] ready
            }
        } else {
            // ---- compute ----
#pragma unroll
            for (int mt = 0; mt < 2; mt++)
#pragma unroll
                for (int nt = 0; nt < 2; nt++)
#pragma unroll
                    for (int q = 0; q < 4; q++) accr[mt][nt][q] = accx[mt][nt][q];

            BAR_SYNC(1, NTHREADS);             // barA

            if (ts > 0) {
                gemm_pipe(aH0, aH1, aBh, accr);    // recurrent GEMM
            }

            // ---- warp-local elementwise (gate shuffle), 4 elems/thread ----
            float hout[2][2];
#pragma unroll
            for (int mt = 0; mt < 2; mt++) {
#pragma unroll
                for (int nt = 0; nt < 2; nt++) {
                    float q0 = accr[mt][nt][0], q1 = accr[mt][nt][1];
                    float q2 = accr[mt][nt][2], q3 = accr[mt][nt][3];
                    float sx = odd ? q0 : q2;
                    float sy = odd ? q1 : q3;
                    float rx = __shfl_xor_sync(0xffffffffu, sx, 1);
                    float ry = __shfl_xor_sync(0xffffffffu, sy, 1);
                    float gi = (odd ? rx : q0) + bias[nt][0];
                    float gf = (odd ? ry : q1) + bias[nt][1];
                    float gg = (odd ? q2 : rx) + bias[nt][2];
                    float go = (odd ? q3 : ry) + bias[nt][3];

                    float iv = fsigmoid(gi), fv = fsigmoid(gf);
                    float gv = ftanh(gg),    ov = fsigmoid(go);
                    float cn = cst[mt][nt] * fv + iv * gv;
                    cst[mt][nt] = cn;
                    float h = ov * ftanh(cn);
                    hout[mt][nt] = h;

                    int rl = mt * 16 + g + (odd << 3);
                    int jl = (warp & 3) * 4 + (t >> 1) + 2 * nt;
                    g_hbuf[ts & 1][(size_t)(b0 + rl) * HID + j0 + jl] =
                        __float2half_rn(h);
                }
            }

            BAR_SYNC(2, 128);                  // compute-only: stores ordered

            if (ts < T_STEPS - 1 && tid == 0) {
                asm volatile("st.release.gpu.global.u32 [%0], %1;"
                             :: "l"(&g_flag[bi][ts][bj]), "r"(1u) : "memory");
            }

            // out fp32 stores (off the inter-block critical path)
            {
                float* obase = out + (size_t)ts * (BATCH * HID);
#pragma unroll
                for (int mt = 0; mt < 2; mt++)
#pragma unroll
                    for (int nt = 0; nt < 2; nt++) {
                        int rl = mt * 16 + g + (odd << 3);
                        int jl = (warp & 3) * 4 + (t >> 1) + 2 * nt;
                        obase[(size_t)(b0 + rl) * HID + j0 + jl] = hout[mt][nt];
                    }
            }

            if (ts + 1 < T_STEPS) {
                BAR_SYNC(3, NTHREADS);         // barB: x[ts+1] in Xh
                xg_gemm();                     // hides loader's poll + h load
            }
        }
    }

    // ---- exit: last block resets barrier state for next graph replay ----
    __syncthreads();
    volatile unsigned* rflag = (volatile unsigned*)(smB + XH_OFF);
    if (tid == 0) {
        unsigned old;
        asm volatile("atom.acq_rel.gpu.add.u32 %0, [%1], 1;"
                     : "=r"(old) : "l"(&g_exit) : "memory");
        *rflag = (old == 127u) ? 1u : 0u;
    }
    __syncthreads();
    if (*rflag != 0u) {
        unsigned int* fl = &g_flag[0][0][0];
        for (int i = tid; i < 4 * T_STEPS * 32; i += NTHREADS) fl[i] = 0u;
        __threadfence();
        if (tid == 0) g_exit = 0u;
    }
}

// ===========================================================================
// Launch
// ===========================================================================
extern "C" void kernel_launch(void* const* d_in, const int* in_sizes, int n_in,
                              void* d_out, int out_size)
{
    (void)in_sizes; (void)n_in; (void)out_size;
    const float* x  = (const float*)d_in[0];
    const float* Wx = (const float*)d_in[1];
    const float* bx = (const float*)d_in[2];
    const float* Wh = (const float*)d_in[3];
    const float* bh = (const float*)d_in[4];
    float* out = (float*)d_out;

    __half* xh;  cudaGetSymbolAddress((void**)&xh,  g_xh);

    cudaFuncSetAttribute(lstm_rec_kernel,
                         cudaFuncAttributeMaxDynamicSharedMemorySize, SMEM_B_BYTES);

    // x: fp32 -> fp16
    cvt_f16_kernel<<<2048, 256>>>(x, xh, (size_t)T_STEPS * BATCH * DIN / 4);

    // fused persistent LSTM
    lstm_rec_kernel<<<128, NTHREADS, SMEM_B_BYTES>>>(Wh, Wx, bx, bh, out);
}